// round 3
// baseline (speedup 1.0000x reference)
#include <cuda_runtime.h>

static constexpr int B = 256;
static constexpr int S = 2048;
static constexpr int T = 48;
static constexpr int HALF = S / 2;

typedef unsigned long long u64;

// ---- packed f32x2 helpers (Blackwell FFMA2: only reachable via PTX) ----
__device__ __forceinline__ u64 pack2(float x, float y) {
    u64 r; asm("mov.b64 %0, {%1, %2};" : "=l"(r) : "f"(x), "f"(y)); return r;
}
__device__ __forceinline__ void unpack2(u64 v, float& x, float& y) {
    asm("mov.b64 {%0, %1}, %2;" : "=f"(x), "=f"(y) : "l"(v));
}
__device__ __forceinline__ u64 ffma2(u64 a, u64 b, u64 c) {
    u64 d; asm("fma.rn.f32x2 %0, %1, %2, %3;" : "=l"(d) : "l"(a), "l"(b), "l"(c)); return d;
}
__device__ __forceinline__ u64 fmul2(u64 a, u64 b) {
    u64 d; asm("mul.rn.f32x2 %0, %1, %2;" : "=l"(d) : "l"(a), "l"(b)); return d;
}
__device__ __forceinline__ u64 fadd2(u64 a, u64 b) {
    u64 d; asm("add.rn.f32x2 %0, %1, %2;" : "=l"(d) : "l"(a), "l"(b)); return d;
}

// exponent-only renormalize: divide p by 2^(e-127) of lane0.x, accumulate e.
__device__ __forceinline__ void renorm_exp(u64& p, int& cexp) {
    float px, py; unpack2(p, px, py);
    float ref = __shfl_sync(0xffffffffu, px, 0);
    int ex = (__float_as_int(ref) >> 23) & 255;
    float sc = __int_as_float((254 - ex) << 23);   // = 2^(127-ex)
    p = fmul2(p, pack2(sc, sc));
    cexp += ex - 127;
}

// TWO scaled-exp-domain semiring chains (same direction, different batches)
// interleaved in one warp for ILP. BW=0: alpha fw (matvec then *exp(e)).
// BW=1: beta bw (*exp(e) then matvec). Lane l owns states (2l,2l+1); lanes
// 24..31 padding (E rows 0 -> p identically 0, slots never read).
template<int BW>
__device__ __forceinline__ void run_chain2(
    const float* __restrict__ epA,   // emissions + bA*S*T + j0
    const float* __restrict__ epB,   // emissions + bB*S*T + j0
    const u64 (&E)[48],
    u64 pA, u64 pB, int niter, int lane,
    float4 (*bufA)[32], float4 (*bufB)[32],
    u64& pOutA, u64& pOutB, float& cOutA, float& cOutB)
{
    int cexpA = 0, cexpB = 0;
    float2 ebA[8], ebB[8];
    int cb = 0;

#define E_OFF(i) ( BW ? (size_t)(S - 1 - (i)) * T : (size_t)((i) + 1) * T )

#pragma unroll
    for (int u = 0; u < 8; ++u)
        if (u < niter) { ebA[u] = *(const float2*)(epA + E_OFF(u));
                         ebB[u] = *(const float2*)(epB + E_OFF(u)); }

#define MATVEC(buf, q) do {                                                \
    u64 a0=0ull,a1=0ull,a2=0ull,a3=0ull,a4=0ull,a5=0ull,a6=0ull,a7=0ull;   \
    _Pragma("unroll")                                                      \
    for (int k = 0; k < 24; k += 4) {                                      \
        float4 v0 = buf[cb][k];                                            \
        a0 = ffma2(E[2*k  ], pack2(v0.x, v0.y), a0);                       \
        a1 = ffma2(E[2*k+1], pack2(v0.z, v0.w), a1);                       \
        float4 v1 = buf[cb][k+1];                                          \
        a2 = ffma2(E[2*k+2], pack2(v1.x, v1.y), a2);                       \
        a3 = ffma2(E[2*k+3], pack2(v1.z, v1.w), a3);                       \
        float4 v2 = buf[cb][k+2];                                          \
        a4 = ffma2(E[2*k+4], pack2(v2.x, v2.y), a4);                       \
        a5 = ffma2(E[2*k+5], pack2(v2.z, v2.w), a5);                       \
        float4 v3 = buf[cb][k+3];                                          \
        a6 = ffma2(E[2*k+6], pack2(v3.x, v3.y), a6);                       \
        a7 = ffma2(E[2*k+7], pack2(v3.z, v3.w), a7);                       \
    }                                                                      \
    q = fadd2(fadd2(fadd2(a0, a1), fadd2(a2, a3)),                         \
              fadd2(fadd2(a4, a5), fadd2(a6, a7)));                        \
} while (0)

#define BODY(i, u, RENORM) do {                                            \
    float2 eA = ebA[u], eB = ebB[u];                                       \
    int tn = (i) + 8;                                                      \
    if (tn < niter) { ebA[u] = *(const float2*)(epA + E_OFF(tn));          \
                      ebB[u] = *(const float2*)(epB + E_OFF(tn)); }        \
    u64 FeA = pack2(__expf(eA.x), __expf(eA.y));                           \
    u64 FeB = pack2(__expf(eB.x), __expf(eB.y));                           \
    u64 srcA = BW ? fmul2(pA, FeA) : pA;                                   \
    u64 srcB = BW ? fmul2(pB, FeB) : pB;                                   \
    { float sx, sy; unpack2(srcA, sx, sy);                                 \
      bufA[cb][lane] = make_float4(sx, sx, sy, sy); }                      \
    { float sx, sy; unpack2(srcB, sx, sy);                                 \
      bufB[cb][lane] = make_float4(sx, sx, sy, sy); }                      \
    __syncwarp();                                                          \
    u64 qA, qB;                                                            \
    MATVEC(bufA, qA);                                                      \
    MATVEC(bufB, qB);                                                      \
    pA = BW ? qA : fmul2(qA, FeA);                                         \
    pB = BW ? qB : fmul2(qB, FeB);                                         \
    cb ^= 1;                                                               \
    if (RENORM) { renorm_exp(pA, cexpA); renorm_exp(pB, cexpB); }          \
} while (0)

    int nmain = niter & ~7;
    for (int i = 0; i < nmain; i += 8) {
#pragma unroll
        for (int u = 0; u < 8; ++u) BODY(i + u, u, (u == 7));
    }
#pragma unroll
    for (int u = 0; u < 8; ++u)
        if (nmain + u < niter) BODY(nmain + u, u, false);

    // final exact renorm so combine products stay well inside fp32 range
    float cA = (float)cexpA * 0.69314718055994531f;
    float cB = (float)cexpB * 0.69314718055994531f;
    {
        float px, py; unpack2(pA, px, py);
        float ref = __shfl_sync(0xffffffffu, px, 0);
        pA = fmul2(pA, pack2(__fdividef(1.f, ref), __fdividef(1.f, ref)));
        cA += __logf(ref);
    }
    {
        float px, py; unpack2(pB, px, py);
        float ref = __shfl_sync(0xffffffffu, px, 0);
        pB = fmul2(pB, pack2(__fdividef(1.f, ref), __fdividef(1.f, ref)));
        cB += __logf(ref);
    }
    pOutA = pA; pOutB = pB; cOutA = cA; cOutB = cB;
#undef BODY
#undef MATVEC
#undef E_OFF
}

__global__ void __launch_bounds__(64)
crf_kernel(const float* __restrict__ emis,
           const int*   __restrict__ tagsw,   // int32 view; int64 auto-detected
           const int*   __restrict__ mask,
           const float* __restrict__ trans,
           const float* __restrict__ startT,
           const float* __restrict__ endT,
           float* __restrict__ out)
{
    __shared__ float4 bufs[2][2][2][32];  // [warp][chain][double-buffer][lane]
    __shared__ float shP[2][48], shR[2][48], shC[2][2];
    __shared__ float shRed[64];

    const int tid = threadIdx.x;
    const int w   = tid >> 5;            // warp 0: forward, warp 1: backward
    const int l   = tid & 31;
    const bool act = l < 24;
    const int j0 = act ? 2*l     : 0;
    const int j1 = act ? 2*l + 1 : 0;

    const int bA = 2 * blockIdx.x;
    const int bB = bA + 1;
    const size_t baseA = (size_t)bA * S * T;
    const size_t baseB = (size_t)bB * S * T;

    // per-lane exp(transition) constants in registers (96 regs, shared by both chains)
    u64 E[48];
    if (w == 0) {
#pragma unroll
        for (int i = 0; i < 48; ++i) {      // column pairs: E[i][j0], E[i][j1]
            float a  = __expf(trans[i*T + j0]);
            float bb = __expf(trans[i*T + j1]);
            E[i] = act ? pack2(a, bb) : 0ull;
        }
    } else {
#pragma unroll
        for (int j = 0; j < 48; ++j) {      // row pairs: E[j0][j], E[j1][j]
            float a  = __expf(trans[j0*T + j]);
            float bb = __expf(trans[j1*T + j]);
            E[j] = act ? pack2(a, bb) : 0ull;
        }
    }

    const float* epA = emis + baseA + j0;
    const float* epB = emis + baseB + j0;

    u64 pfA, pfB; float cfA, cfB;
    if (w == 0) {
        float2 e0A = *(const float2*)(epA);
        float2 e0B = *(const float2*)(epB);
        u64 p0A = act ? pack2(__expf(startT[j0] + e0A.x),
                              __expf(startT[j1] + e0A.y)) : 0ull;
        u64 p0B = act ? pack2(__expf(startT[j0] + e0B.x),
                              __expf(startT[j1] + e0B.y)) : 0ull;
        run_chain2<0>(epA, epB, E, p0A, p0B, HALF - 1, l,
                      bufs[0][0], bufs[0][1], pfA, pfB, cfA, cfB);
    } else {
        u64 p0 = act ? pack2(__expf(endT[j0]), __expf(endT[j1])) : 0ull;
        run_chain2<1>(epA, epB, E, p0, p0, HALF, l,
                      bufs[1][0], bufs[1][1], pfA, pfB, cfA, cfB);
    }

    if (act) {
        float px, py;
        unpack2(pfA, px, py);
        if (w == 0) { shP[0][2*l] = px; shP[0][2*l+1] = py; }
        else        { shR[0][2*l] = px; shR[0][2*l+1] = py; }
        unpack2(pfB, px, py);
        if (w == 0) { shP[1][2*l] = px; shP[1][2*l+1] = py; }
        else        { shR[1][2*l] = px; shR[1][2*l+1] = py; }
    }
    if (l == 0) { shC[w][0] = cfA; shC[w][1] = cfB; }
    __syncthreads();

    // ---- denominators Z for both batches ----
    // lanes 0..47 handle batch0 product, reuse shRed twice
    float Z[2];
#pragma unroll
    for (int bi = 0; bi < 2; ++bi) {
        shRed[tid] = (tid < 48) ? shP[bi][tid] * shR[bi][tid] : 0.f;
        __syncthreads();
        if (tid == 0) {
            float dot = 0.f;
#pragma unroll
            for (int k = 0; k < 48; ++k) dot += shRed[k];
            Z[bi] = __logf(dot) + shC[0][bi] + shC[1][bi];
        }
        __syncthreads();
    }

    // ---- tags dtype detection: int64 iff sampled odd 32-bit words all zero ----
    int oddw = tagsw[2*tid + 1];
    int any  = __syncthreads_or(oddw != 0);
    const bool is64 = (any == 0);

    // ---- numerators: gold-path scores for both batches ----
#pragma unroll
    for (int bi = 0; bi < 2; ++bi) {
        const int    b     = bA + bi;
        const size_t base  = (size_t)b * S * T;
        const size_t tbase = (size_t)b * S;
        float num = 0.f;
#pragma unroll 4
        for (int k = 0; k < 32; ++k) {
            int s = tid + 64*k;
            int cur = is64 ? tagsw[(tbase + s) * 2] : tagsw[tbase + s];
            if (s == 0) {
                num += startT[cur] + emis[base + cur];
            } else {
                int prev = is64 ? tagsw[(tbase + s - 1) * 2] : tagsw[tbase + s - 1];
                float m = (float)mask[tbase + s];
                num += (trans[prev*T + cur] + emis[base + (size_t)s*T + cur]) * m;
            }
            if (s == S - 1) num += endT[cur];
        }
        shRed[tid] = num;
        __syncthreads();
        if (tid == 0) {
            float tot = 0.f;
#pragma unroll
            for (int k = 0; k < 64; ++k) tot += shRed[k];
            out[b] = Z[bi] - tot;
        }
        __syncthreads();
    }
}

extern "C" void kernel_launch(void* const* d_in, const int* in_sizes, int n_in,
                              void* d_out, int out_size) {
    (void)in_sizes; (void)n_in; (void)out_size;
    crf_kernel<<<B / 2, 64>>>(
        (const float*)d_in[0],   // emissions
        (const int*)  d_in[1],   // tags (i32 or i64, detected on device)
        (const int*)  d_in[2],   // mask
        (const float*)d_in[3],   // transitions
        (const float*)d_in[4],   // start_transitions
        (const float*)d_in[5],   // end_transitions
        (float*)d_out);
}

// round 4
// speedup vs baseline: 2.1352x; 2.1352x over previous
#include <cuda_runtime.h>

static constexpr int B = 256;
static constexpr int S = 2048;
static constexpr int T = 48;
static constexpr int HALF = S / 2;

typedef unsigned long long u64;

// ---- packed f32x2 helpers (Blackwell FFMA2: only reachable via PTX) ----
__device__ __forceinline__ u64 pack2(float x, float y) {
    u64 r; asm("mov.b64 %0, {%1, %2};" : "=l"(r) : "f"(x), "f"(y)); return r;
}
__device__ __forceinline__ void unpack2(u64 v, float& x, float& y) {
    asm("mov.b64 {%0, %1}, %2;" : "=f"(x), "=f"(y) : "l"(v));
}
__device__ __forceinline__ u64 ffma2(u64 a, u64 b, u64 c) {
    u64 d; asm("fma.rn.f32x2 %0, %1, %2, %3;" : "=l"(d) : "l"(a), "l"(b), "l"(c)); return d;
}
__device__ __forceinline__ u64 fadd2(u64 a, u64 b) {
    u64 d; asm("add.rn.f32x2 %0, %1, %2;" : "=l"(d) : "l"(a), "l"(b)); return d;
}

// One scaled-exp-domain semiring chain, shuffle-based all-to-all (no smem).
// Lane l owns states (2l, 2l+1) as scalars (px, py); lanes 24..31 padding
// (their E pairs are 0 -> their state stays identically 0).
// BW=0: alpha forward  p' = (E^T p) * f      (f = exp(emission))
// BW=1: beta  backward p' = E (p * f)
template<int BW>
__device__ __forceinline__ void run_chain(
    const float* __restrict__ ep0,     // emissions + b*S*T + j0
    const u64 (&EA)[24], const u64 (&EB)[24],
    float px, float py, int niter,
    float& pxOut, float& pyOut, float& cOut)
{
    int cexp = 0;
    float2 ebuf[8];

#define E_OFF(i) ( BW ? (size_t)(S - 1 - (i)) * T : (size_t)((i) + 1) * T )

#pragma unroll
    for (int u = 0; u < 8; ++u)
        if (u < niter) ebuf[u] = *(const float2*)(ep0 + E_OFF(u));

#define BODY(i, u, RENORM) do {                                            \
    float2 e = ebuf[u];                                                    \
    int tn = (i) + 8;                                                      \
    if (tn < niter) ebuf[u] = *(const float2*)(ep0 + E_OFF(tn));           \
    float fex = __expf(e.x);                                               \
    float fey = __expf(e.y);                                               \
    float sx = BW ? px * fex : px;                                         \
    float sy = BW ? py * fey : py;                                         \
    u64 a0=0ull,a1=0ull,a2=0ull,a3=0ull,a4=0ull,a5=0ull,a6=0ull,a7=0ull;   \
    _Pragma("unroll")                                                      \
    for (int k = 0; k < 24; k += 4) {                                      \
        u64 b0 = pack2(__shfl_sync(0xffffffffu, sx, k),                    \
                       __shfl_sync(0xffffffffu, sy, k));                   \
        a0 = ffma2(EA[k],   b0, a0);                                       \
        a4 = ffma2(EB[k],   b0, a4);                                       \
        u64 b1 = pack2(__shfl_sync(0xffffffffu, sx, k+1),                  \
                       __shfl_sync(0xffffffffu, sy, k+1));                 \
        a1 = ffma2(EA[k+1], b1, a1);                                       \
        a5 = ffma2(EB[k+1], b1, a5);                                       \
        u64 b2 = pack2(__shfl_sync(0xffffffffu, sx, k+2),                  \
                       __shfl_sync(0xffffffffu, sy, k+2));                 \
        a2 = ffma2(EA[k+2], b2, a2);                                       \
        a6 = ffma2(EB[k+2], b2, a6);                                       \
        u64 b3 = pack2(__shfl_sync(0xffffffffu, sx, k+3),                  \
                       __shfl_sync(0xffffffffu, sy, k+3));                 \
        a3 = ffma2(EA[k+3], b3, a3);                                       \
        a7 = ffma2(EB[k+3], b3, a7);                                       \
    }                                                                      \
    u64 qa = fadd2(fadd2(a0, a1), fadd2(a2, a3));                          \
    u64 qb = fadd2(fadd2(a4, a5), fadd2(a6, a7));                          \
    float qax, qay; unpack2(qa, qax, qay);                                 \
    float qbx, qby; unpack2(qb, qbx, qby);                                 \
    px = BW ? (qax + qay) : (qax + qay) * fex;                             \
    py = BW ? (qbx + qby) : (qbx + qby) * fey;                             \
    if (RENORM) {                                                          \
        float ref = __shfl_sync(0xffffffffu, px, 0);                       \
        int ex = (__float_as_int(ref) >> 23) & 255;                        \
        float sc = __int_as_float((254 - ex) << 23);   /* 2^(127-ex) */    \
        px *= sc; py *= sc;                                                \
        cexp += ex - 127;                                                  \
    }                                                                      \
} while (0)

    int nmain = niter & ~7;
    for (int i = 0; i < nmain; i += 8) {
#pragma unroll
        for (int u = 0; u < 8; ++u) BODY(i + u, u, (u == 7));
    }
#pragma unroll
    for (int u = 0; u < 8; ++u)
        if (nmain + u < niter) BODY(nmain + u, u, false);

    // final exact renorm so combine products stay well inside fp32 range
    float c = (float)cexp * 0.69314718055994531f;
    {
        float ref = __shfl_sync(0xffffffffu, px, 0);
        float inv = __fdividef(1.f, ref);
        px *= inv; py *= inv;
        c += __logf(ref);
    }
    pxOut = px; pyOut = py; cOut = c;
#undef BODY
#undef E_OFF
}

__global__ void __launch_bounds__(64)
crf_kernel(const float* __restrict__ emis,
           const int*   __restrict__ tagsw,   // int32 view; int64 auto-detected
           const int*   __restrict__ mask,
           const float* __restrict__ trans,
           const float* __restrict__ startT,
           const float* __restrict__ endT,
           float* __restrict__ out)
{
    __shared__ float shP[48], shR[48], shC[2];
    __shared__ float shRed[64];

    const int b   = blockIdx.x;
    const int tid = threadIdx.x;
    const int w   = tid >> 5;            // warp 0: forward, warp 1: backward
    const int l   = tid & 31;
    const bool act = l < 24;
    const int j0 = act ? 2*l     : 0;
    const int j1 = act ? 2*l + 1 : 0;

    const size_t base = (size_t)b * S * T;

    // per-lane exp(transition) pair constants in registers (96 regs).
    // fw: EA[k] = (E[2k][j0], E[2k+1][j0]),  EB[k] = (E[2k][j1], E[2k+1][j1])
    // bw: EA[k] = (E[j0][2k], E[j0][2k+1]),  EB[k] = (E[j1][2k], E[j1][2k+1])
    u64 EA[24], EB[24];
    if (w == 0) {
#pragma unroll
        for (int k = 0; k < 24; ++k) {
            float a0 = __expf(trans[(2*k)*T   + j0]);
            float a1 = __expf(trans[(2*k+1)*T + j0]);
            float b0 = __expf(trans[(2*k)*T   + j1]);
            float b1 = __expf(trans[(2*k+1)*T + j1]);
            EA[k] = act ? pack2(a0, a1) : 0ull;
            EB[k] = act ? pack2(b0, b1) : 0ull;
        }
    } else {
#pragma unroll
        for (int k = 0; k < 24; ++k) {
            float a0 = __expf(trans[j0*T + 2*k]);
            float a1 = __expf(trans[j0*T + 2*k+1]);
            float b0 = __expf(trans[j1*T + 2*k]);
            float b1 = __expf(trans[j1*T + 2*k+1]);
            EA[k] = act ? pack2(a0, a1) : 0ull;
            EB[k] = act ? pack2(b0, b1) : 0ull;
        }
    }

    const float* ep0 = emis + base + j0;

    float pfx, pfy, cfin;
    if (w == 0) {
        float2 e0 = *(const float2*)(ep0);                    // t = 0
        float p0x = act ? __expf(startT[j0] + e0.x) : 0.f;
        float p0y = act ? __expf(startT[j1] + e0.y) : 0.f;
        run_chain<0>(ep0, EA, EB, p0x, p0y, HALF - 1, pfx, pfy, cfin);
    } else {
        float p0x = act ? __expf(endT[j0]) : 0.f;
        float p0y = act ? __expf(endT[j1]) : 0.f;
        run_chain<1>(ep0, EA, EB, p0x, p0y, HALF,     pfx, pfy, cfin);
    }

    if (act) {
        if (w == 0) { shP[2*l] = pfx; shP[2*l+1] = pfy; }
        else        { shR[2*l] = pfx; shR[2*l+1] = pfy; }
    }
    if (l == 0) shC[w] = cfin;
    __syncthreads();

    shRed[tid] = (tid < 48) ? shP[tid] * shR[tid] : 0.f;
    __syncthreads();

    float Z = 0.f;
    if (tid == 0) {
        float dot = 0.f;
#pragma unroll
        for (int k = 0; k < 48; ++k) dot += shRed[k];
        Z = __logf(dot) + shC[0] + shC[1];          // log-partition (denominator)
    }

    // ---- tags dtype detection: int64 iff sampled odd 32-bit words all zero ----
    int oddw = tagsw[2*tid + 1];
    int any  = __syncthreads_or(oddw != 0);          // also a barrier for shRed reuse
    const bool is64 = (any == 0);

    // ---- numerator: gold-path score ----
    const size_t tbase = (size_t)b * S;
    float num = 0.f;
#pragma unroll 4
    for (int k = 0; k < 32; ++k) {
        int s = tid + 64*k;
        int cur = is64 ? tagsw[(tbase + s) * 2] : tagsw[tbase + s];
        if (s == 0) {
            num += startT[cur] + emis[base + cur];
        } else {
            int prev = is64 ? tagsw[(tbase + s - 1) * 2] : tagsw[tbase + s - 1];
            float m = (float)mask[tbase + s];
            num += (trans[prev*T + cur] + emis[base + (size_t)s*T + cur]) * m;
        }
        if (s == S - 1) num += endT[cur];
    }
    shRed[tid] = num;
    __syncthreads();
    if (tid == 0) {
        float tot = 0.f;
#pragma unroll
        for (int k = 0; k < 64; ++k) tot += shRed[k];
        out[b] = Z - tot;                            // NLL
    }
}

extern "C" void kernel_launch(void* const* d_in, const int* in_sizes, int n_in,
                              void* d_out, int out_size) {
    (void)in_sizes; (void)n_in; (void)out_size;
    crf_kernel<<<B, 64>>>(
        (const float*)d_in[0],   // emissions
        (const int*)  d_in[1],   // tags (i32 or i64, detected on device)
        (const int*)  d_in[2],   // mask
        (const float*)d_in[3],   // transitions
        (const float*)d_in[4],   // start_transitions
        (const float*)d_in[5],   // end_transitions
        (float*)d_out);
}